// round 7
// baseline (speedup 1.0000x reference)
#include <cuda_runtime.h>
#include <mma.h>
#include <cstdint>

using namespace nvcuda;

#define B_  4
#define S_  2048
#define D_  1024
#define H_  16
#define DK_ 64

__device__ float g_Q [(size_t)B_*S_*D_];
__device__ float g_K [(size_t)B_*S_*D_];
__device__ float g_V [(size_t)B_*S_*D_];
__device__ float g_AO[(size_t)B_*S_*D_];

#define TF32(x) wmma::__float_to_tf32(x)

__device__ __forceinline__ void cpasync16(uint32_t saddr, const float* g) {
    asm volatile("cp.async.cg.shared.global [%0], [%1], 16;" :: "r"(saddr), "l"(g));
}
__device__ __forceinline__ void cpasync_commit() {
    asm volatile("cp.async.commit_group;");
}
__device__ __forceinline__ void cpasync_wait0() {
    asm volatile("cp.async.wait_group 0;");
}

// ---------------------------------------------------------------------------
// Pipelined tf32 NT GEMM body: C = A @ B^T + bias, all dims 1024/8192 fixed.
// BM=BN=128, BK=32, double-buffered smem, 1 barrier per slab.
// tf32 rounding once at smem store. ROUND -> outputs tf32-rounded.
// ---------------------------------------------------------------------------
#define LDP 36

template<int ROUND>
__device__ __forceinline__ void gemm_body(
    const float* __restrict__ A, const float* __restrict__ Bm,
    const float* __restrict__ bias, float* __restrict__ C,
    float* As, float* Bs, float* Cs)
{
    const int tid  = threadIdx.x;
    const int w    = tid >> 5, lane = tid & 31;
    const int wm   = w >> 2, wn = w & 3;
    const size_t m0 = (size_t)blockIdx.y * 128;
    const size_t n0 = (size_t)blockIdx.x * 128;

    const int lrow = tid >> 3, lc4 = tid & 7;   // 128 rows x 8 float4 (x4 its)

    wmma::fragment<wmma::accumulator, 16, 16, 8, float> c[4][2];
#pragma unroll
    for (int i = 0; i < 4; i++)
#pragma unroll
        for (int j = 0; j < 2; j++) wmma::fill_fragment(c[i][j], 0.f);

    float4 av[4], bv[4];
#pragma unroll
    for (int it = 0; it < 4; it++) {
        int row = lrow + 32 * it;
        av[it] = *(const float4*)(A  + (m0 + row) * 1024 + lc4 * 4);
        bv[it] = *(const float4*)(Bm + (n0 + row) * 1024 + lc4 * 4);
    }
#pragma unroll
    for (int it = 0; it < 4; it++) {
        int row = lrow + 32 * it;
        float4 a = av[it], b = bv[it];
        a.x = TF32(a.x); a.y = TF32(a.y); a.z = TF32(a.z); a.w = TF32(a.w);
        b.x = TF32(b.x); b.y = TF32(b.y); b.z = TF32(b.z); b.w = TF32(b.w);
        *(float4*)&As[row * LDP + lc4 * 4] = a;
        *(float4*)&Bs[row * LDP + lc4 * 4] = b;
    }
    __syncthreads();

    for (int kb = 0; kb < 32; kb++) {
        float* as = As + (kb & 1) * (128 * LDP);
        float* bs = Bs + (kb & 1) * (128 * LDP);
        if (kb < 31) {
            const int k0 = (kb + 1) * 32;
#pragma unroll
            for (int it = 0; it < 4; it++) {
                int row = lrow + 32 * it;
                av[it] = *(const float4*)(A  + (m0 + row) * 1024 + k0 + lc4 * 4);
                bv[it] = *(const float4*)(Bm + (n0 + row) * 1024 + k0 + lc4 * 4);
            }
        }
#pragma unroll
        for (int ks = 0; ks < 4; ks++) {
            wmma::fragment<wmma::matrix_a, 16, 16, 8, wmma::precision::tf32, wmma::row_major> a[4];
            wmma::fragment<wmma::matrix_b, 16, 16, 8, wmma::precision::tf32, wmma::col_major> b[2];
#pragma unroll
            for (int i = 0; i < 4; i++)
                wmma::load_matrix_sync(a[i], &as[(64 * wm + 16 * i) * LDP + ks * 8], LDP);
#pragma unroll
            for (int j = 0; j < 2; j++)
                wmma::load_matrix_sync(b[j], &bs[(32 * wn + 16 * j) * LDP + ks * 8], LDP);
#pragma unroll
            for (int i = 0; i < 4; i++)
#pragma unroll
                for (int j = 0; j < 2; j++)
                    wmma::mma_sync(c[i][j], a[i], b[j], c[i][j]);
        }
        if (kb < 31) {
            float* asn = As + ((kb + 1) & 1) * (128 * LDP);
            float* bsn = Bs + ((kb + 1) & 1) * (128 * LDP);
#pragma unroll
            for (int it = 0; it < 4; it++) {
                int row = lrow + 32 * it;
                float4 a = av[it], b = bv[it];
                a.x = TF32(a.x); a.y = TF32(a.y); a.z = TF32(a.z); a.w = TF32(a.w);
                b.x = TF32(b.x); b.y = TF32(b.y); b.z = TF32(b.z); b.w = TF32(b.w);
                *(float4*)&asn[row * LDP + lc4 * 4] = a;
                *(float4*)&bsn[row * LDP + lc4 * 4] = b;
            }
        }
        __syncthreads();
    }

    float* buf = Cs + w * 320;
#pragma unroll
    for (int i = 0; i < 4; i++) {
#pragma unroll
        for (int j = 0; j < 2; j++) {
            wmma::store_matrix_sync(buf, c[i][j], 20, wmma::mem_row_major);
            __syncwarp();
            const int rr = lane >> 1, ch = (lane & 1) * 8;
            const size_t gr = m0 + 64 * wm + 16 * i + rr;
            const size_t gc = n0 + 32 * wn + 16 * j + ch;
            float4 v0 = *(float4*)&buf[rr * 20 + ch];
            float4 v1 = *(float4*)&buf[rr * 20 + ch + 4];
            v0.x += bias[gc + 0]; v0.y += bias[gc + 1];
            v0.z += bias[gc + 2]; v0.w += bias[gc + 3];
            v1.x += bias[gc + 4]; v1.y += bias[gc + 5];
            v1.z += bias[gc + 6]; v1.w += bias[gc + 7];
            if (ROUND) {
                v0.x = TF32(v0.x); v0.y = TF32(v0.y); v0.z = TF32(v0.z); v0.w = TF32(v0.w);
                v1.x = TF32(v1.x); v1.y = TF32(v1.y); v1.z = TF32(v1.z); v1.w = TF32(v1.w);
            }
            *(float4*)(C + gr * 1024 + gc)     = v0;
            *(float4*)(C + gr * 1024 + gc + 4) = v1;
            __syncwarp();
        }
    }
}

#define GEMM_SMEM_FLOATS (2 * 128 * LDP * 2 + 8 * 320)

// Combined Q/K/V projection: grid z picks which of the three.
__global__ __launch_bounds__(256) void qkv_proj(
    const float* __restrict__ q,  const float* __restrict__ k,
    const float* __restrict__ v,
    const float* __restrict__ Wq, const float* __restrict__ bq,
    const float* __restrict__ Wk, const float* __restrict__ bk,
    const float* __restrict__ Wv, const float* __restrict__ bv,
    float* __restrict__ Qo, float* __restrict__ Ko, float* __restrict__ Vo)
{
    __shared__ float smem[GEMM_SMEM_FLOATS];
    float* As = smem;
    float* Bs = smem + 2 * 128 * LDP;
    float* Cs = smem + 4 * 128 * LDP;
    const float *A, *W, *bi; float* C;
    if (blockIdx.z == 0)      { A = q; W = Wq; bi = bq; C = Qo; }
    else if (blockIdx.z == 1) { A = k; W = Wk; bi = bk; C = Ko; }
    else                      { A = v; W = Wv; bi = bv; C = Vo; }
    gemm_body<1>(A, W, bi, C, As, Bs, Cs);
}

__global__ __launch_bounds__(256) void out_proj(
    const float* __restrict__ A, const float* __restrict__ W,
    const float* __restrict__ bi, float* __restrict__ C)
{
    __shared__ float smem[GEMM_SMEM_FLOATS];
    gemm_body<0>(A, W, bi, C, smem, smem + 2 * 128 * LDP, smem + 4 * 128 * LDP);
}

// ---------------------------------------------------------------------------
// Fused attention per (q-tile 128, head). Q/K/V pre-rounded tf32.
// exp + tf32 rounding done elementwise IN the S fragments; P written
// unnormalized then rescaled in-kernel by the same threads (thread-local).
// Smem: Ps [128*72] @0, Kb[2] @9216, Vb[2] @18432. 110592 B, 2 CTAs/SM.
// ---------------------------------------------------------------------------
#define FA_SMEM_BYTES  (27648 * 4)
#define KB_OFF 9216
#define VB_OFF 18432
#define KVSTRIDE 4608

__global__ __launch_bounds__(256, 2) void fused_attn(
    const float* __restrict__ Q, const float* __restrict__ K,
    const float* __restrict__ V, float* __restrict__ P,
    float* __restrict__ AO)
{
    extern __shared__ float sm[];
    float* Ps = sm;
    const uint32_t smem_u32 = (uint32_t)__cvta_generic_to_shared(sm);

    const int tid = threadIdx.x, w = tid >> 5;
    const int wm = w >> 1, wn = w & 1;
    const int bh = blockIdx.y, b = bh >> 4, h = bh & 15;
    const int q0 = blockIdx.x * 128;
    const int prow = tid >> 4;
    const int pc4  = tid & 15;

    const float* Qb = Q + (size_t)b * S_ * D_ + h * DK_;
    const float* Kb = K + (size_t)b * S_ * D_ + h * DK_;
    const float* Vb = V + (size_t)b * S_ * D_ + h * DK_;
    float* Pb = P + (size_t)bh * S_ * S_;

    // ---- Stage Q tile -> Ps, load register fragments ----
#pragma unroll
    for (int it = 0; it < 8; it++) {
        int idx = tid + 256 * it;
        int row = idx >> 4, c4 = idx & 15;
        *(float4*)&Ps[row * 72 + c4 * 4] =
            *(const float4*)(Qb + (size_t)(q0 + row) * D_ + c4 * 4);
    }
    __syncthreads();
    wmma::fragment<wmma::matrix_a, 16, 16, 8, wmma::precision::tf32, wmma::row_major> Qf[8][2];
#pragma unroll
    for (int ks = 0; ks < 8; ks++)
#pragma unroll
        for (int i = 0; i < 2; i++)
            wmma::load_matrix_sync(Qf[ks][i], &Ps[(32 * wm + 16 * i) * 72 + ks * 8], 72);
    __syncthreads();   // Ps free for S tiles

    float rs[8];
#pragma unroll
    for (int i = 0; i < 8; i++) rs[i] = 0.f;

    wmma::fragment<wmma::accumulator, 16, 16, 8, float> c_o[2][2];
#pragma unroll
    for (int i = 0; i < 2; i++)
#pragma unroll
        for (int j = 0; j < 2; j++) wmma::fill_fragment(c_o[i][j], 0.f);

    // prologue: chunk 0
#pragma unroll
    for (int it = 0; it < 4; it++) {
        int row = prow + 16 * it;
        cpasync16(smem_u32 + (KB_OFF + row * 72 + pc4 * 4) * 4,
                  Kb + (size_t)row * D_ + pc4 * 4);
        cpasync16(smem_u32 + (VB_OFF + row * 72 + pc4 * 4) * 4,
                  Vb + (size_t)row * D_ + pc4 * 4);
    }
    cpasync_commit();

    for (int kc = 0; kc < 32; kc++) {
        const int cur = kc & 1;
        float* Kc = sm + KB_OFF + cur * KVSTRIDE;
        float* Vc = sm + VB_OFF + cur * KVSTRIDE;

        cpasync_wait0();
        __syncthreads();   // K/V ready; prev chunk fully done with Ps + buffers

        if (kc + 1 < 32) {
            const int nxt = 1 - cur;
#pragma unroll
            for (int it = 0; it < 4; it++) {
                int row = prow + 16 * it;
                cpasync16(smem_u32 + (KB_OFF + nxt * KVSTRIDE + row * 72 + pc4 * 4) * 4,
                          Kb + (size_t)((kc + 1) * 64 + row) * D_ + pc4 * 4);
                cpasync16(smem_u32 + (VB_OFF + nxt * KVSTRIDE + row * 72 + pc4 * 4) * 4,
                          Vb + (size_t)((kc + 1) * 64 + row) * D_ + pc4 * 4);
            }
            cpasync_commit();
        }

        // ---- S = Q @ Kc^T ----
        wmma::fragment<wmma::accumulator, 16, 16, 8, float> c_s[2][2];
#pragma unroll
        for (int i = 0; i < 2; i++)
#pragma unroll
            for (int j = 0; j < 2; j++) wmma::fill_fragment(c_s[i][j], 0.f);
#pragma unroll
        for (int ks = 0; ks < 8; ks++) {
            wmma::fragment<wmma::matrix_b, 16, 16, 8, wmma::precision::tf32, wmma::col_major> bb[2];
#pragma unroll
            for (int j = 0; j < 2; j++)
                wmma::load_matrix_sync(bb[j], &Kc[(32 * wn + 16 * j) * 72 + ks * 8], 72);
#pragma unroll
            for (int i = 0; i < 2; i++)
#pragma unroll
                for (int j = 0; j < 2; j++)
                    wmma::mma_sync(c_s[i][j], Qf[ks][i], bb[j], c_s[i][j]);
        }

        // ---- exp + tf32 round elementwise IN fragments, store once ----
#pragma unroll
        for (int i = 0; i < 2; i++)
#pragma unroll
            for (int j = 0; j < 2; j++) {
#pragma unroll
                for (int e = 0; e < c_s[i][j].num_elements; e++)
                    c_s[i][j].x[e] = TF32(__expf(c_s[i][j].x[e] * 0.125f));
                wmma::store_matrix_sync(&Ps[(32 * wm + 16 * i) * 72 + 32 * wn + 16 * j],
                                        c_s[i][j], 72, wmma::mem_row_major);
            }
        __syncthreads();

        // ---- pass: rowsums + gmem P write (reads Ps) ----
#pragma unroll
        for (int it = 0; it < 8; it++) {
            int row = prow + 16 * it;
            float4 v = *(float4*)&Ps[row * 72 + pc4 * 4];
            float s = v.x + v.y + v.z + v.w;
            s += __shfl_xor_sync(0xffffffffu, s, 1);
            s += __shfl_xor_sync(0xffffffffu, s, 2);
            s += __shfl_xor_sync(0xffffffffu, s, 4);
            s += __shfl_xor_sync(0xffffffffu, s, 8);
            rs[it] += s;
            *(float4*)(Pb + (size_t)(q0 + row) * S_ + kc * 64 + pc4 * 4) = v;
        }

        // ---- O += Ps @ Vc ----
#pragma unroll
        for (int ks = 0; ks < 8; ks++) {
            wmma::fragment<wmma::matrix_a, 16, 16, 8, wmma::precision::tf32, wmma::row_major> a2[2];
            wmma::fragment<wmma::matrix_b, 16, 16, 8, wmma::precision::tf32, wmma::row_major> b2[2];
#pragma unroll
            for (int i = 0; i < 2; i++)
                wmma::load_matrix_sync(a2[i], &Ps[(32 * wm + 16 * i) * 72 + ks * 8], 72);
#pragma unroll
            for (int j = 0; j < 2; j++)
                wmma::load_matrix_sync(b2[j], &Vc[(ks * 8) * 72 + 32 * wn + 16 * j], 72);
#pragma unroll
            for (int i = 0; i < 2; i++)
#pragma unroll
                for (int j = 0; j < 2; j++)
                    wmma::mma_sync(c_o[i][j], a2[i], b2[j], c_o[i][j]);
        }
    }

    // ---- in-kernel rescale of P: each thread rescales exactly what it wrote
#pragma unroll
    for (int it = 0; it < 8; it++) {
        const int row = prow + 16 * it;
        const float inv = 1.0f / rs[it];
        float* base = Pb + (size_t)(q0 + row) * S_ + pc4 * 4;
#pragma unroll 8
        for (int kc = 0; kc < 32; kc++) {
            float4 v = *(float4*)(base + kc * 64);
            v.x *= inv; v.y *= inv; v.z *= inv; v.w *= inv;
            *(float4*)(base + kc * 64) = v;
        }
    }

    __syncthreads();   // all warps done reading Ps (PV of last chunk)

    // ---- O staging + AO write ----
#pragma unroll
    for (int i = 0; i < 2; i++)
#pragma unroll
        for (int j = 0; j < 2; j++)
            wmma::store_matrix_sync(&Ps[(32 * wm + 16 * i) * 72 + 32 * wn + 16 * j],
                                    c_o[i][j], 72, wmma::mem_row_major);
    __syncthreads();

#pragma unroll
    for (int it = 0; it < 8; it++) {
        int row = prow + 16 * it;
        const float inv = 1.0f / rs[it];
        float4 v = *(float4*)&Ps[row * 72 + pc4 * 4];
        v.x = TF32(v.x * inv); v.y = TF32(v.y * inv);
        v.z = TF32(v.z * inv); v.w = TF32(v.w * inv);
        *(float4*)(AO + ((size_t)b * S_ + q0 + row) * D_ + h * DK_ + pc4 * 4) = v;
    }
}

// ---------------------------------------------------------------------------
extern "C" void kernel_launch(void* const* d_in, const int* in_sizes, int n_in,
                              void* d_out, int out_size)
{
    const float* query = (const float*)d_in[0];
    const float* key_  = (const float*)d_in[1];
    const float* value = (const float*)d_in[2];
    const float* Wq = (const float*)d_in[3];
    const float* bq = (const float*)d_in[4];
    const float* Wk = (const float*)d_in[5];
    const float* bk = (const float*)d_in[6];
    const float* Wv = (const float*)d_in[7];
    const float* bv = (const float*)d_in[8];
    const float* Wo = (const float*)d_in[9];
    const float* bo = (const float*)d_in[10];

    float* out  = (float*)d_out;
    float* attn = out + (size_t)B_ * S_ * D_;

    float *Qp, *Kp, *Vp, *AOp;
    cudaGetSymbolAddress((void**)&Qp,  g_Q);
    cudaGetSymbolAddress((void**)&Kp,  g_K);
    cudaGetSymbolAddress((void**)&Vp,  g_V);
    cudaGetSymbolAddress((void**)&AOp, g_AO);

    cudaFuncSetAttribute(fused_attn,
                         cudaFuncAttributeMaxDynamicSharedMemorySize,
                         FA_SMEM_BYTES);

    const dim3 blk(256);

    qkv_proj<<<dim3(8, 64, 3), blk>>>(query, key_, value,
                                      Wq, bq, Wk, bk, Wv, bv,
                                      Qp, Kp, Vp);

    fused_attn<<<dim3(16, 64), blk, FA_SMEM_BYTES>>>(Qp, Kp, Vp, attn, AOp);

    out_proj<<<dim3(8, 64), blk>>>(AOp, Wo, bo, out);
}